// round 4
// baseline (speedup 1.0000x reference)
#include <cuda_runtime.h>
#include <cuda_bf16.h>
#include <math.h>
#include <stdint.h>

#define BATCH    512
#define NTOK     100
#define HD       768
#define ID       1536
#define M_ROWS   (BATCH * NTOK)     // 51200
#define BM       128
#define ROW_BLKS (M_ROWS / BM)      // 400
#define BN       128
#define N_PASSES (ID / BN)          // 12
#define KP       2304               // 3 * 768 virtual K
#define BK       32
#define KT_PER   (KP / BK)          // 72
#define STAGES   8
#define APITCH   80                 // smem bytes per row (32 bf16 + 8 pad)
#define A_STAGE_B (BM * APITCH)     // 10240
#define B_STAGE_B (BN * APITCH)     // 10240
#define STAGE_B   (A_STAGE_B + B_STAGE_B)  // 20480
#define SM_B1S    (STAGES * STAGE_B)       // 163840
#define SM_SGW    (SM_B1S + ID * 4)        // 169984
#define SM_RED    (SM_SGW + ID * 4)        // 176128
#define SMEM_TOTAL (SM_RED + 2 * BM * 3 * 4)  // 179200
#define LN_EPS   1e-5f

__device__ float g_c1, g_c2;

// A2: [M][1536] bf16 = [Ah(768) | Al(768)]
__device__ __align__(16) __nv_bfloat16 A2[(size_t)M_ROWS * ID];
// Bt: [N=1536][2304] bf16 = per row n: [Bh(768) | Bl(768) | Bh(768)]
__device__ __align__(16) __nv_bfloat16 Bt[(size_t)ID * KP];

// ------------------------------- helpers -----------------------------------
__device__ __forceinline__ uint32_t smem_u32(const void* p) {
    uint32_t a;
    asm("{ .reg .u64 t; cvta.to.shared.u64 t, %1; cvt.u32.u64 %0, t; }" : "=r"(a) : "l"(p));
    return a;
}

__device__ __forceinline__ void cp16(uint32_t dst, const void* src) {
    asm volatile("cp.async.cg.shared.global [%0], [%1], 16;" :: "r"(dst), "l"(src));
}
#define CP_COMMIT() asm volatile("cp.async.commit_group;" ::: "memory")
#define CP_WAIT6()  asm volatile("cp.async.wait_group 6;" ::: "memory")
#define CP_WAIT0()  asm volatile("cp.async.wait_group 0;" ::: "memory")

#define LDSM4(r0, r1, r2, r3, addr) \
    asm volatile("ldmatrix.sync.aligned.m8n8.x4.shared.b16 {%0,%1,%2,%3}, [%4];" \
                 : "=r"(r0), "=r"(r1), "=r"(r2), "=r"(r3) : "r"(addr))

#define MMA16816(d, a, bx, by) \
    asm volatile("mma.sync.aligned.m16n8k16.row.col.f32.bf16.bf16.f32 " \
                 "{%0,%1,%2,%3},{%4,%5,%6,%7},{%8,%9},{%0,%1,%2,%3};" \
                 : "+f"((d)[0]), "+f"((d)[1]), "+f"((d)[2]), "+f"((d)[3]) \
                 : "r"((a)[0]), "r"((a)[1]), "r"((a)[2]), "r"((a)[3]), "r"(bx), "r"(by))

// ------------------------------ prep kernels -------------------------------
__global__ void consts_kernel(const float* __restrict__ gamma,
                              const float* __restrict__ beta,
                              const float* __restrict__ W2,
                              const float* __restrict__ b2) {
    __shared__ float s1s[8], s2s[8];
    int tid = threadIdx.x;
    float c1 = 0.f, c2 = 0.f;
    for (int i = tid; i < ID; i += blockDim.x) {
        float w = W2[i];
        c1 += gamma[i] * w;
        c2 += beta[i] * w;
    }
    for (int o = 16; o; o >>= 1) {
        c1 += __shfl_xor_sync(0xffffffffu, c1, o);
        c2 += __shfl_xor_sync(0xffffffffu, c2, o);
    }
    if ((tid & 31) == 0) { s1s[tid >> 5] = c1; s2s[tid >> 5] = c2; }
    __syncthreads();
    if (tid == 0) {
        float a = 0.f, b = 0.f;
        for (int w = 0; w < (int)(blockDim.x >> 5); w++) { a += s1s[w]; b += s2s[w]; }
        g_c1 = a;
        g_c2 = b + b2[0];
    }
}

__global__ void splitA_kernel(const float* __restrict__ A) {
    size_t idx = (size_t)blockIdx.x * 256 + threadIdx.x;
    int m  = (int)(idx / (HD / 4));
    int k4 = (int)(idx % (HD / 4)) * 4;
    float4 v = *(const float4*)(A + (size_t)m * HD + k4);
    float vs[4] = {v.x, v.y, v.z, v.w};
    __nv_bfloat16 h[4], l[4];
#pragma unroll
    for (int e = 0; e < 4; e++) {
        h[e] = __float2bfloat16(vs[e]);
        l[e] = __float2bfloat16(vs[e] - __bfloat162float(h[e]));
    }
    __nv_bfloat162* dh = (__nv_bfloat162*)(A2 + (size_t)m * ID + k4);
    __nv_bfloat162* dl = (__nv_bfloat162*)(A2 + (size_t)m * ID + HD + k4);
    dh[0] = __halves2bfloat162(h[0], h[1]);
    dh[1] = __halves2bfloat162(h[2], h[3]);
    dl[0] = __halves2bfloat162(l[0], l[1]);
    dl[1] = __halves2bfloat162(l[2], l[3]);
}

__global__ void splitB_kernel(const float* __restrict__ W1) {
    int idx = blockIdx.x * 256 + threadIdx.x;
    int k  = idx / (ID / 4);
    int n4 = (idx % (ID / 4)) * 4;
    float4 v = *(const float4*)(W1 + (size_t)k * ID + n4);
    float vs[4] = {v.x, v.y, v.z, v.w};
#pragma unroll
    for (int e = 0; e < 4; e++) {
        int n = n4 + e;
        __nv_bfloat16 h = __float2bfloat16(vs[e]);
        __nv_bfloat16 l = __float2bfloat16(vs[e] - __bfloat162float(h));
        size_t base = (size_t)n * KP + k;
        Bt[base]        = h;
        Bt[base + 768]  = l;
        Bt[base + 1536] = h;
    }
}

// ------------------------------ GEMM stage issue ----------------------------
__device__ __forceinline__ void issue_tile(uint32_t sb, int s, int rb, int nt, int kt, int tid) {
    int acol = (kt % 24) * 32 + (kt >= 48 ? HD : 0);
    const __nv_bfloat16* gA = A2 + (size_t)rb * BM * ID + acol;
    uint32_t dA = sb + s * STAGE_B;
#pragma unroll
    for (int j = 0; j < 2; j++) {
        int c = tid + 256 * j;          // 0..511
        int row = c >> 2, c16 = c & 3;
        cp16(dA + row * APITCH + c16 * 16, gA + (size_t)row * ID + c16 * 8);
    }
    const __nv_bfloat16* gB = Bt + (size_t)nt * BN * KP + kt * 32;
    uint32_t dB = sb + s * STAGE_B + A_STAGE_B;
#pragma unroll
    for (int j = 0; j < 2; j++) {
        int c = tid + 256 * j;          // 0..511
        int row = c >> 2, c16 = c & 3;
        cp16(dB + row * APITCH + c16 * 16, gB + (size_t)row * KP + c16 * 8);
    }
}

// ------------------------------ GEMM kernel --------------------------------
// 256 threads (8 warps): warp grid 4(M) x 2(N), warp tile 32x64, mma m16n8k16.
__global__ __launch_bounds__(256, 1)
void gemm_kernel(const float* __restrict__ b1,
                 const float* __restrict__ gamma,
                 const float* __restrict__ W2,
                 float* __restrict__ scores) {
    extern __shared__ char smem[];
    const uint32_t sb = smem_u32(smem);
    float* b1s = (float*)(smem + SM_B1S);
    float* sgw = (float*)(smem + SM_SGW);
    float* red = (float*)(smem + SM_RED);   // [2][128][3]
    const int tid = threadIdx.x, wid = tid >> 5, lane = tid & 31;
    const int wm = wid & 3, wn = wid >> 2;
    const int rb = blockIdx.x;

    for (int i = tid; i < ID; i += 256) {
        b1s[i] = b1[i];
        sgw[i] = gamma[i] * W2[i];
    }

    const uint32_t a_off = (uint32_t)((wm * 32 + (lane & 15)) * APITCH + (lane >> 4) * 16);
    const uint32_t b_off = (uint32_t)(A_STAGE_B
                          + (wn * 64 + ((lane & 7) | ((lane >> 4) << 3))) * APITCH
                          + ((lane >> 3) & 1) * 16);

    float acc[2][8][4];
    float s1[4], s2[4], s3[4];
#pragma unroll
    for (int r = 0; r < 4; r++) { s1[r] = 0.f; s2[r] = 0.f; s3[r] = 0.f; }

    int nt_p = 0, kt_p = 0;
#pragma unroll
    for (int s = 0; s < STAGES - 1; s++) {
        issue_tile(sb, s, rb, nt_p, kt_p, tid);
        CP_COMMIT();
        if (++kt_p == KT_PER) { kt_p = 0; nt_p++; }
    }

    int i = 0;
    for (int nt = 0; nt < N_PASSES; nt++) {
#pragma unroll
        for (int mt = 0; mt < 2; mt++)
#pragma unroll
            for (int j = 0; j < 8; j++)
#pragma unroll
                for (int cc = 0; cc < 4; cc++) acc[mt][j][cc] = 0.f;

        for (int kt = 0; kt < KT_PER; kt++, i++) {
            CP_WAIT6();
            __syncthreads();
            if (nt_p < N_PASSES) {
                issue_tile(sb, (i + STAGES - 1) & (STAGES - 1), rb, nt_p, kt_p, tid);
                if (++kt_p == KT_PER) { kt_p = 0; nt_p++; }
            }
            CP_COMMIT();

            const uint32_t stg = sb + (uint32_t)(i & (STAGES - 1)) * STAGE_B;
#pragma unroll
            for (int k16 = 0; k16 < 2; k16++) {
                uint32_t a0[4], a1[4], bb[4][4];
                LDSM4(a0[0], a0[1], a0[2], a0[3], stg + a_off + k16 * 32);
                LDSM4(a1[0], a1[1], a1[2], a1[3], stg + a_off + 16 * APITCH + k16 * 32);
#pragma unroll
                for (int np = 0; np < 4; np++) {
                    LDSM4(bb[np][0], bb[np][1], bb[np][2], bb[np][3],
                          stg + b_off + np * 16 * APITCH + k16 * 32);
                }
#pragma unroll
                for (int np = 0; np < 4; np++) {
                    MMA16816(acc[0][2 * np],     a0, bb[np][0], bb[np][1]);
                    MMA16816(acc[0][2 * np + 1], a0, bb[np][2], bb[np][3]);
                    MMA16816(acc[1][2 * np],     a1, bb[np][0], bb[np][1]);
                    MMA16816(acc[1][2 * np + 1], a1, bb[np][2], bb[np][3]);
                }
            }
        }

        // ---- fused epilogue: bias + exact GELU + LN moments (registers) ----
        const int nb = nt * BN + wn * 64;
#pragma unroll
        for (int mt = 0; mt < 2; mt++)
#pragma unroll
            for (int j = 0; j < 8; j++)
#pragma unroll
                for (int cc = 0; cc < 4; cc++) {
                    int half = cc >> 1, cp = cc & 1;
                    int n = nb + j * 8 + (lane & 3) * 2 + cp;
                    float h = acc[mt][j][cc] + b1s[n];
                    float g = 0.5f * h * (1.0f + erff(h * 0.70710678118654752f));
                    int ridx = mt * 2 + half;
                    s1[ridx] += g;
                    s2[ridx] += g * g;
                    s3[ridx] += g * sgw[n];
                }
    }
    CP_WAIT0();

    // quad-reduce LN moments (lanes sharing rows)
#pragma unroll
    for (int r = 0; r < 4; r++) {
        s1[r] += __shfl_xor_sync(0xffffffffu, s1[r], 1);
        s1[r] += __shfl_xor_sync(0xffffffffu, s1[r], 2);
        s2[r] += __shfl_xor_sync(0xffffffffu, s2[r], 1);
        s2[r] += __shfl_xor_sync(0xffffffffu, s2[r], 2);
        s3[r] += __shfl_xor_sync(0xffffffffu, s3[r], 1);
        s3[r] += __shfl_xor_sync(0xffffffffu, s3[r], 2);
    }
    __syncthreads();

    // cross-warp (wn) partials to smem
    if ((lane & 3) == 0) {
#pragma unroll
        for (int mt = 0; mt < 2; mt++)
#pragma unroll
            for (int half = 0; half < 2; half++) {
                int ridx = mt * 2 + half;
                int rl = wm * 32 + mt * 16 + (lane >> 2) + half * 8;
                float* p = red + (wn * BM + rl) * 3;
                p[0] = s1[ridx]; p[1] = s2[ridx]; p[2] = s3[ridx];
            }
    }
    __syncthreads();

    if (tid < BM) {
        const float c1 = g_c1, c2 = g_c2, inv = 1.0f / (float)ID;
        float* p0 = red + tid * 3;
        float* p1 = red + (BM + tid) * 3;
        float t1 = p0[0] + p1[0];
        float t2 = p0[1] + p1[1];
        float t3 = p0[2] + p1[2];
        float mu   = t1 * inv;
        float var  = t2 * inv - mu * mu;
        float rstd = rsqrtf(var + LN_EPS);
        float x = rstd * (t3 - mu * c1) + c2;
        scores[rb * BM + tid] = 1.0f / (1.0f + expf(-x));
    }
}

// ------------------------------ finalize -----------------------------------
__global__ void finalize_kernel(const float* __restrict__ scores,
                                float* __restrict__ pred,
                                float* __restrict__ logits) {
    int b = blockIdx.x;
    int tid = threadIdx.x;   // 128
    float v = (tid < NTOK) ? scores[b * NTOK + tid] : 0.f;
    for (int o = 16; o; o >>= 1) v += __shfl_xor_sync(0xffffffffu, v, o);
    __shared__ float ws[4];
    __shared__ float predv;
    if ((tid & 31) == 0) ws[tid >> 5] = v;
    __syncthreads();
    if (tid == 0) {
        float s = ws[0] + ws[1] + ws[2] + ws[3];
        pred[b] = s;
        predv = s;
    }
    __syncthreads();
    if (tid < 16) {
        int aid = (int)rintf(predv);
        aid = min(max(aid, 0), 15);
        logits[b * 16 + tid] = (tid == aid) ? 1.0f : 0.0f;
    }
}

// ------------------------------ launch --------------------------------------
extern "C" void kernel_launch(void* const* d_in, const int* in_sizes, int n_in,
                              void* d_out, int out_size) {
    const float* v_emb = (const float*)d_in[0];
    const float* W1    = (const float*)d_in[1];
    const float* b1    = (const float*)d_in[2];
    const float* gamma = (const float*)d_in[3];
    const float* beta  = (const float*)d_in[4];
    const float* W2    = (const float*)d_in[5];
    const float* b2    = (const float*)d_in[6];

    float* out    = (float*)d_out;
    float* scores = out;                    // [51200]
    float* pred   = out + M_ROWS;           // [512]
    float* logits = out + M_ROWS + BATCH;   // [512*16]

    cudaFuncSetAttribute(gemm_kernel, cudaFuncAttributeMaxDynamicSharedMemorySize, SMEM_TOTAL);

    consts_kernel<<<1, 256>>>(gamma, beta, W2, b2);
    splitA_kernel<<<(M_ROWS * (HD / 4)) / 256, 256>>>(v_emb);
    splitB_kernel<<<(HD * (ID / 4)) / 256, 256>>>(W1);
    gemm_kernel<<<ROW_BLKS, 256, SMEM_TOTAL>>>(b1, gamma, W2, scores);
    finalize_kernel<<<BATCH, 128>>>(scores, pred, logits);
}

// round 5
// speedup vs baseline: 1.1469x; 1.1469x over previous
#include <cuda_runtime.h>
#include <cuda_bf16.h>
#include <math.h>
#include <stdint.h>

#define BATCH    512
#define NTOK     100
#define HD       768
#define ID       1536
#define M_ROWS   (BATCH * NTOK)     // 51200
#define BM       64
#define ROW_BLKS (M_ROWS / BM)      // 800
#define BN       128
#define N_PASSES (ID / BN)          // 12
#define KP       2304               // 3 * 768 virtual K
#define BK       32
#define KT_PER   (KP / BK)          // 72
#define STAGES   4
#define APITCH   80                 // smem bytes per row (32 bf16 + 8 pad)
#define A_STAGE_B (BM * APITCH)     // 5120
#define B_STAGE_B (BN * APITCH)     // 10240
#define STAGE_B   (A_STAGE_B + B_STAGE_B)  // 15360
#define SM_B1S    (STAGES * STAGE_B)       // 61440
#define SM_SGW    (SM_B1S + ID * 4)        // 67584
#define SM_RED    (SM_SGW + ID * 4)        // 73728
#define SMEM_TOTAL (SM_RED + 2 * BM * 3 * 4)  // 75264
#define LN_EPS   1e-5f

__device__ float g_c1, g_c2;

// A2: [M][1536] bf16 = [Ah(768) | Al(768)]
__device__ __align__(16) __nv_bfloat16 A2[(size_t)M_ROWS * ID];
// Bt: [N=1536][2304] bf16 = per row n: [Bh(768) | Bl(768) | Bh(768)]
__device__ __align__(16) __nv_bfloat16 Bt[(size_t)ID * KP];

// ------------------------------- helpers -----------------------------------
__device__ __forceinline__ uint32_t smem_u32(const void* p) {
    uint32_t a;
    asm("{ .reg .u64 t; cvta.to.shared.u64 t, %1; cvt.u32.u64 %0, t; }" : "=r"(a) : "l"(p));
    return a;
}

__device__ __forceinline__ void cp16(uint32_t dst, const void* src) {
    asm volatile("cp.async.cg.shared.global [%0], [%1], 16;" :: "r"(dst), "l"(src));
}
#define CP_COMMIT() asm volatile("cp.async.commit_group;" ::: "memory")
#define CP_WAIT2()  asm volatile("cp.async.wait_group 2;" ::: "memory")
#define CP_WAIT0()  asm volatile("cp.async.wait_group 0;" ::: "memory")

#define LDSM4(r0, r1, r2, r3, addr) \
    asm volatile("ldmatrix.sync.aligned.m8n8.x4.shared.b16 {%0,%1,%2,%3}, [%4];" \
                 : "=r"(r0), "=r"(r1), "=r"(r2), "=r"(r3) : "r"(addr))

#define MMA16816(d, a, bx, by) \
    asm volatile("mma.sync.aligned.m16n8k16.row.col.f32.bf16.bf16.f32 " \
                 "{%0,%1,%2,%3},{%4,%5,%6,%7},{%8,%9},{%0,%1,%2,%3};" \
                 : "+f"((d)[0]), "+f"((d)[1]), "+f"((d)[2]), "+f"((d)[3]) \
                 : "r"((a)[0]), "r"((a)[1]), "r"((a)[2]), "r"((a)[3]), "r"(bx), "r"(by))

// ------------------------------ prep kernels -------------------------------
__global__ void consts_kernel(const float* __restrict__ gamma,
                              const float* __restrict__ beta,
                              const float* __restrict__ W2,
                              const float* __restrict__ b2) {
    __shared__ float s1s[8], s2s[8];
    int tid = threadIdx.x;
    float c1 = 0.f, c2 = 0.f;
    for (int i = tid; i < ID; i += blockDim.x) {
        float w = W2[i];
        c1 += gamma[i] * w;
        c2 += beta[i] * w;
    }
    for (int o = 16; o; o >>= 1) {
        c1 += __shfl_xor_sync(0xffffffffu, c1, o);
        c2 += __shfl_xor_sync(0xffffffffu, c2, o);
    }
    if ((tid & 31) == 0) { s1s[tid >> 5] = c1; s2s[tid >> 5] = c2; }
    __syncthreads();
    if (tid == 0) {
        float a = 0.f, b = 0.f;
        for (int w = 0; w < (int)(blockDim.x >> 5); w++) { a += s1s[w]; b += s2s[w]; }
        g_c1 = a;
        g_c2 = b + b2[0];
    }
}

__global__ void splitA_kernel(const float* __restrict__ A) {
    size_t idx = (size_t)blockIdx.x * 256 + threadIdx.x;
    int m  = (int)(idx / (HD / 4));
    int k4 = (int)(idx % (HD / 4)) * 4;
    float4 v = *(const float4*)(A + (size_t)m * HD + k4);
    float vs[4] = {v.x, v.y, v.z, v.w};
    __nv_bfloat16 h[4], l[4];
#pragma unroll
    for (int e = 0; e < 4; e++) {
        h[e] = __float2bfloat16(vs[e]);
        l[e] = __float2bfloat16(vs[e] - __bfloat162float(h[e]));
    }
    __nv_bfloat162* dh = (__nv_bfloat162*)(A2 + (size_t)m * ID + k4);
    __nv_bfloat162* dl = (__nv_bfloat162*)(A2 + (size_t)m * ID + HD + k4);
    dh[0] = __halves2bfloat162(h[0], h[1]);
    dh[1] = __halves2bfloat162(h[2], h[3]);
    dl[0] = __halves2bfloat162(l[0], l[1]);
    dl[1] = __halves2bfloat162(l[2], l[3]);
}

__global__ void splitB_kernel(const float* __restrict__ W1) {
    int idx = blockIdx.x * 256 + threadIdx.x;
    int k  = idx / (ID / 4);
    int n4 = (idx % (ID / 4)) * 4;
    float4 v = *(const float4*)(W1 + (size_t)k * ID + n4);
    float vs[4] = {v.x, v.y, v.z, v.w};
#pragma unroll
    for (int e = 0; e < 4; e++) {
        int n = n4 + e;
        __nv_bfloat16 h = __float2bfloat16(vs[e]);
        __nv_bfloat16 l = __float2bfloat16(vs[e] - __bfloat162float(h));
        size_t base = (size_t)n * KP + k;
        Bt[base]        = h;
        Bt[base + 768]  = l;
        Bt[base + 1536] = h;
    }
}

// ------------------------------ GEMM stage issue ----------------------------
__device__ __forceinline__ void issue_tile(uint32_t sb, int s, int rb, int nt, int kt, int tid) {
    int acol = (kt % 24) * 32 + (kt >= 48 ? HD : 0);
    const __nv_bfloat16* gA = A2 + (size_t)rb * BM * ID + acol;
    uint32_t dA = sb + s * STAGE_B;
    {
        int c = tid * 2;                // 0..254, two consecutive c16 per thread
        int row = c >> 2, c16 = c & 3;
        cp16(dA + row * APITCH + c16 * 16, gA + (size_t)row * ID + c16 * 8);
        cp16(dA + row * APITCH + (c16 + 1) * 16, gA + (size_t)row * ID + (c16 + 1) * 8);
    }
    const __nv_bfloat16* gB = Bt + (size_t)nt * BN * KP + kt * 32;
    uint32_t dB = sb + s * STAGE_B + A_STAGE_B;
#pragma unroll
    for (int j = 0; j < 4; j++) {
        int c = tid + 128 * j;          // 0..511
        int row = c >> 2, c16 = c & 3;
        cp16(dB + row * APITCH + c16 * 16, gB + (size_t)row * KP + c16 * 8);
    }
}

// ------------------------------ GEMM kernel --------------------------------
// 128 threads (4 warps): warp grid 2(M) x 2(N), warp tile 32x64, mma m16n8k16.
__global__ __launch_bounds__(128, 3)
void gemm_kernel(const float* __restrict__ b1,
                 const float* __restrict__ gamma,
                 const float* __restrict__ W2,
                 float* __restrict__ scores) {
    extern __shared__ char smem[];
    const uint32_t sb = smem_u32(smem);
    float* b1s = (float*)(smem + SM_B1S);
    float* sgw = (float*)(smem + SM_SGW);
    float* red = (float*)(smem + SM_RED);   // [2][64][3]
    const int tid = threadIdx.x, wid = tid >> 5, lane = tid & 31;
    const int wm = wid & 1, wn = wid >> 1;
    const int rb = blockIdx.x;

    for (int i = tid; i < ID; i += 128) {
        b1s[i] = b1[i];
        sgw[i] = gamma[i] * W2[i];
    }

    const uint32_t a_off = (uint32_t)((wm * 32 + (lane & 15)) * APITCH + (lane >> 4) * 16);
    const uint32_t b_off = (uint32_t)(A_STAGE_B
                          + (wn * 64 + ((lane & 7) | ((lane >> 4) << 3))) * APITCH
                          + ((lane >> 3) & 1) * 16);

    float acc[2][8][4];
    float s1[4], s2[4], s3[4];
#pragma unroll
    for (int r = 0; r < 4; r++) { s1[r] = 0.f; s2[r] = 0.f; s3[r] = 0.f; }

    int nt_p = 0, kt_p = 0;
#pragma unroll
    for (int s = 0; s < STAGES - 1; s++) {
        issue_tile(sb, s, rb, nt_p, kt_p, tid);
        CP_COMMIT();
        if (++kt_p == KT_PER) { kt_p = 0; nt_p++; }
    }

    int i = 0;
    for (int nt = 0; nt < N_PASSES; nt++) {
#pragma unroll
        for (int mt = 0; mt < 2; mt++)
#pragma unroll
            for (int j = 0; j < 8; j++)
#pragma unroll
                for (int cc = 0; cc < 4; cc++) acc[mt][j][cc] = 0.f;

        for (int kt = 0; kt < KT_PER; kt++, i++) {
            CP_WAIT2();
            __syncthreads();
            if (nt_p < N_PASSES) {
                issue_tile(sb, (i + STAGES - 1) & (STAGES - 1), rb, nt_p, kt_p, tid);
                if (++kt_p == KT_PER) { kt_p = 0; nt_p++; }
            }
            CP_COMMIT();

            const uint32_t stg = sb + (uint32_t)(i & (STAGES - 1)) * STAGE_B;
#pragma unroll
            for (int k16 = 0; k16 < 2; k16++) {
                uint32_t a0[4], a1[4], bb[4][4];
                LDSM4(a0[0], a0[1], a0[2], a0[3], stg + a_off + k16 * 32);
                LDSM4(a1[0], a1[1], a1[2], a1[3], stg + a_off + 16 * APITCH + k16 * 32);
#pragma unroll
                for (int np = 0; np < 4; np++) {
                    LDSM4(bb[np][0], bb[np][1], bb[np][2], bb[np][3],
                          stg + b_off + np * 16 * APITCH + k16 * 32);
                }
#pragma unroll
                for (int np = 0; np < 4; np++) {
                    MMA16816(acc[0][2 * np],     a0, bb[np][0], bb[np][1]);
                    MMA16816(acc[0][2 * np + 1], a0, bb[np][2], bb[np][3]);
                    MMA16816(acc[1][2 * np],     a1, bb[np][0], bb[np][1]);
                    MMA16816(acc[1][2 * np + 1], a1, bb[np][2], bb[np][3]);
                }
            }
        }

        // ---- fused epilogue: bias + exact GELU + LN moments (registers) ----
        const int nb = nt * BN + wn * 64;
#pragma unroll
        for (int mt = 0; mt < 2; mt++)
#pragma unroll
            for (int j = 0; j < 8; j++)
#pragma unroll
                for (int cc = 0; cc < 4; cc++) {
                    int half = cc >> 1, cp = cc & 1;
                    int n = nb + j * 8 + (lane & 3) * 2 + cp;
                    float h = acc[mt][j][cc] + b1s[n];
                    float g = 0.5f * h * (1.0f + erff(h * 0.70710678118654752f));
                    int ridx = mt * 2 + half;
                    s1[ridx] += g;
                    s2[ridx] += g * g;
                    s3[ridx] += g * sgw[n];
                }
    }
    CP_WAIT0();

    // quad-reduce LN moments (lanes sharing rows)
#pragma unroll
    for (int r = 0; r < 4; r++) {
        s1[r] += __shfl_xor_sync(0xffffffffu, s1[r], 1);
        s1[r] += __shfl_xor_sync(0xffffffffu, s1[r], 2);
        s2[r] += __shfl_xor_sync(0xffffffffu, s2[r], 1);
        s2[r] += __shfl_xor_sync(0xffffffffu, s2[r], 2);
        s3[r] += __shfl_xor_sync(0xffffffffu, s3[r], 1);
        s3[r] += __shfl_xor_sync(0xffffffffu, s3[r], 2);
    }
    __syncthreads();

    // cross-warp (wn) partials to smem
    if ((lane & 3) == 0) {
#pragma unroll
        for (int mt = 0; mt < 2; mt++)
#pragma unroll
            for (int half = 0; half < 2; half++) {
                int ridx = mt * 2 + half;
                int rl = wm * 32 + mt * 16 + (lane >> 2) + half * 8;
                float* p = red + (wn * BM + rl) * 3;
                p[0] = s1[ridx]; p[1] = s2[ridx]; p[2] = s3[ridx];
            }
    }
    __syncthreads();

    if (tid < BM) {
        const float c1 = g_c1, c2 = g_c2, inv = 1.0f / (float)ID;
        float* p0 = red + tid * 3;
        float* p1 = red + (BM + tid) * 3;
        float t1 = p0[0] + p1[0];
        float t2 = p0[1] + p1[1];
        float t3 = p0[2] + p1[2];
        float mu   = t1 * inv;
        float var  = t2 * inv - mu * mu;
        float rstd = rsqrtf(var + LN_EPS);
        float x = rstd * (t3 - mu * c1) + c2;
        scores[rb * BM + tid] = 1.0f / (1.0f + expf(-x));
    }
}

// ------------------------------ finalize -----------------------------------
__global__ void finalize_kernel(const float* __restrict__ scores,
                                float* __restrict__ pred,
                                float* __restrict__ logits) {
    int b = blockIdx.x;
    int tid = threadIdx.x;   // 128
    float v = (tid < NTOK) ? scores[b * NTOK + tid] : 0.f;
    for (int o = 16; o; o >>= 1) v += __shfl_xor_sync(0xffffffffu, v, o);
    __shared__ float ws[4];
    __shared__ float predv;
    if ((tid & 31) == 0) ws[tid >> 5] = v;
    __syncthreads();
    if (tid == 0) {
        float s = ws[0] + ws[1] + ws[2] + ws[3];
        pred[b] = s;
        predv = s;
    }
    __syncthreads();
    if (tid < 16) {
        int aid = (int)rintf(predv);
        aid = min(max(aid, 0), 15);
        logits[b * 16 + tid] = (tid == aid) ? 1.0f : 0.0f;
    }
}

// ------------------------------ launch --------------------------------------
extern "C" void kernel_launch(void* const* d_in, const int* in_sizes, int n_in,
                              void* d_out, int out_size) {
    const float* v_emb = (const float*)d_in[0];
    const float* W1    = (const float*)d_in[1];
    const float* b1    = (const float*)d_in[2];
    const float* gamma = (const float*)d_in[3];
    const float* beta  = (const float*)d_in[4];
    const float* W2    = (const float*)d_in[5];
    const float* b2    = (const float*)d_in[6];

    float* out    = (float*)d_out;
    float* scores = out;                    // [51200]
    float* pred   = out + M_ROWS;           // [512]
    float* logits = out + M_ROWS + BATCH;   // [512*16]

    cudaFuncSetAttribute(gemm_kernel, cudaFuncAttributeMaxDynamicSharedMemorySize, SMEM_TOTAL);

    consts_kernel<<<1, 256>>>(gamma, beta, W2, b2);
    splitA_kernel<<<(M_ROWS * (HD / 4)) / 256, 256>>>(v_emb);
    splitB_kernel<<<(HD * (ID / 4)) / 256, 256>>>(W1);
    gemm_kernel<<<ROW_BLKS, 128, SMEM_TOTAL>>>(b1, gamma, W2, scores);
    finalize_kernel<<<BATCH, 128>>>(scores, pred, logits);
}

// round 6
// speedup vs baseline: 1.1994x; 1.0457x over previous
#include <cuda_runtime.h>
#include <cuda_bf16.h>
#include <math.h>
#include <stdint.h>

#define BATCH    512
#define NTOK     100
#define HD       768
#define ID       1536
#define M_ROWS   (BATCH * NTOK)     // 51200
#define BM       128
#define ROW_BLKS (M_ROWS / BM)      // 400
#define BN       128
#define N_PASSES (ID / BN)          // 12
#define KP       2304               // 3 * 768 virtual K
#define BK       32
#define KT_PER   (KP / BK)          // 72
#define STAGES   4
#define APITCH   80                 // smem bytes per row (32 bf16 + 8 pad)
#define A_STAGE_B (BM * APITCH)     // 10240
#define B_STAGE_B (BN * APITCH)     // 10240
#define STAGE_B   (A_STAGE_B + B_STAGE_B)  // 20480
#define SM_B1S    (STAGES * STAGE_B)       // 81920
#define SM_SGW    (SM_B1S + ID * 4)        // 88064
#define SM_RED    (SM_SGW + ID * 4)        // 94208
#define SMEM_TOTAL (SM_RED + 2 * BM * 3 * 4)  // 97280
#define LN_EPS   1e-5f

__device__ float g_c1, g_c2;

// A2: [M][1536] bf16 = [Ah(768) | Al(768)]
__device__ __align__(16) __nv_bfloat16 A2[(size_t)M_ROWS * ID];
// Bt: [N=1536][2304] bf16 = per row n: [Bh(768) | Bl(768) | Bh(768)]
__device__ __align__(16) __nv_bfloat16 Bt[(size_t)ID * KP];

// ------------------------------- helpers -----------------------------------
__device__ __forceinline__ uint32_t smem_u32(const void* p) {
    uint32_t a;
    asm("{ .reg .u64 t; cvta.to.shared.u64 t, %1; cvt.u32.u64 %0, t; }" : "=r"(a) : "l"(p));
    return a;
}

__device__ __forceinline__ void cp16(uint32_t dst, const void* src) {
    asm volatile("cp.async.cg.shared.global [%0], [%1], 16;" :: "r"(dst), "l"(src));
}
#define CP_COMMIT() asm volatile("cp.async.commit_group;" ::: "memory")
#define CP_WAIT2()  asm volatile("cp.async.wait_group 2;" ::: "memory")
#define CP_WAIT0()  asm volatile("cp.async.wait_group 0;" ::: "memory")

#define LDSM4(r0, r1, r2, r3, addr) \
    asm volatile("ldmatrix.sync.aligned.m8n8.x4.shared.b16 {%0,%1,%2,%3}, [%4];" \
                 : "=r"(r0), "=r"(r1), "=r"(r2), "=r"(r3) : "r"(addr))

#define MMA16816(d, a, bx, by) \
    asm volatile("mma.sync.aligned.m16n8k16.row.col.f32.bf16.bf16.f32 " \
                 "{%0,%1,%2,%3},{%4,%5,%6,%7},{%8,%9},{%0,%1,%2,%3};" \
                 : "+f"((d)[0]), "+f"((d)[1]), "+f"((d)[2]), "+f"((d)[3]) \
                 : "r"((a)[0]), "r"((a)[1]), "r"((a)[2]), "r"((a)[3]), "r"(bx), "r"(by))

// ------------------------------ prep kernels -------------------------------
__global__ void consts_kernel(const float* __restrict__ gamma,
                              const float* __restrict__ beta,
                              const float* __restrict__ W2,
                              const float* __restrict__ b2) {
    __shared__ float s1s[8], s2s[8];
    int tid = threadIdx.x;
    float c1 = 0.f, c2 = 0.f;
    for (int i = tid; i < ID; i += blockDim.x) {
        float w = W2[i];
        c1 += gamma[i] * w;
        c2 += beta[i] * w;
    }
    for (int o = 16; o; o >>= 1) {
        c1 += __shfl_xor_sync(0xffffffffu, c1, o);
        c2 += __shfl_xor_sync(0xffffffffu, c2, o);
    }
    if ((tid & 31) == 0) { s1s[tid >> 5] = c1; s2s[tid >> 5] = c2; }
    __syncthreads();
    if (tid == 0) {
        float a = 0.f, b = 0.f;
        for (int w = 0; w < (int)(blockDim.x >> 5); w++) { a += s1s[w]; b += s2s[w]; }
        g_c1 = a;
        g_c2 = b + b2[0];
    }
}

__global__ void splitA_kernel(const float* __restrict__ A) {
    size_t idx = (size_t)blockIdx.x * 256 + threadIdx.x;
    int m  = (int)(idx / (HD / 4));
    int k4 = (int)(idx % (HD / 4)) * 4;
    float4 v = *(const float4*)(A + (size_t)m * HD + k4);
    float vs[4] = {v.x, v.y, v.z, v.w};
    __nv_bfloat16 h[4], l[4];
#pragma unroll
    for (int e = 0; e < 4; e++) {
        h[e] = __float2bfloat16(vs[e]);
        l[e] = __float2bfloat16(vs[e] - __bfloat162float(h[e]));
    }
    __nv_bfloat162* dh = (__nv_bfloat162*)(A2 + (size_t)m * ID + k4);
    __nv_bfloat162* dl = (__nv_bfloat162*)(A2 + (size_t)m * ID + HD + k4);
    dh[0] = __halves2bfloat162(h[0], h[1]);
    dh[1] = __halves2bfloat162(h[2], h[3]);
    dl[0] = __halves2bfloat162(l[0], l[1]);
    dl[1] = __halves2bfloat162(l[2], l[3]);
}

__global__ void splitB_kernel(const float* __restrict__ W1) {
    int idx = blockIdx.x * 256 + threadIdx.x;
    int k  = idx / (ID / 4);
    int n4 = (idx % (ID / 4)) * 4;
    float4 v = *(const float4*)(W1 + (size_t)k * ID + n4);
    float vs[4] = {v.x, v.y, v.z, v.w};
#pragma unroll
    for (int e = 0; e < 4; e++) {
        int n = n4 + e;
        __nv_bfloat16 h = __float2bfloat16(vs[e]);
        __nv_bfloat16 l = __float2bfloat16(vs[e] - __bfloat162float(h));
        size_t base = (size_t)n * KP + k;
        Bt[base]        = h;
        Bt[base + 768]  = l;
        Bt[base + 1536] = h;
    }
}

// ------------------------------ GEMM stage issue ----------------------------
__device__ __forceinline__ void issue_tile(uint32_t sb, int s, int rb, int nt, int kt, int tid) {
    int acol = (kt % 24) * 32 + (kt >= 48 ? HD : 0);
    const __nv_bfloat16* gA = A2 + (size_t)rb * BM * ID + acol;
    uint32_t dA = sb + s * STAGE_B;
#pragma unroll
    for (int j = 0; j < 4; j++) {
        int c = tid + 128 * j;          // 0..511
        int row = c >> 2, c16 = c & 3;
        cp16(dA + row * APITCH + c16 * 16, gA + (size_t)row * ID + c16 * 8);
    }
    const __nv_bfloat16* gB = Bt + (size_t)nt * BN * KP + kt * 32;
    uint32_t dB = sb + s * STAGE_B + A_STAGE_B;
#pragma unroll
    for (int j = 0; j < 4; j++) {
        int c = tid + 128 * j;          // 0..511
        int row = c >> 2, c16 = c & 3;
        cp16(dB + row * APITCH + c16 * 16, gB + (size_t)row * KP + c16 * 8);
    }
}

// ------------------------------ GEMM kernel --------------------------------
// 128 threads (4 warps): warp grid 2(M) x 2(N), warp tile 64x64, mma m16n8k16.
__global__ __launch_bounds__(128, 2)
void gemm_kernel(const float* __restrict__ b1,
                 const float* __restrict__ gamma,
                 const float* __restrict__ W2,
                 float* __restrict__ scores) {
    extern __shared__ char smem[];
    const uint32_t sb = smem_u32(smem);
    float* b1s = (float*)(smem + SM_B1S);
    float* sgw = (float*)(smem + SM_SGW);
    float* red = (float*)(smem + SM_RED);   // [2][128][3]
    const int tid = threadIdx.x, wid = tid >> 5, lane = tid & 31;
    const int wm = wid & 1, wn = wid >> 1;
    const int rb = blockIdx.x;

    for (int i = tid; i < ID; i += 128) {
        b1s[i] = b1[i];
        sgw[i] = gamma[i] * W2[i];
    }

    const uint32_t a_off = (uint32_t)((wm * 64 + (lane & 15)) * APITCH + (lane >> 4) * 16);
    const uint32_t b_off = (uint32_t)(A_STAGE_B
                          + (wn * 64 + ((lane & 7) | ((lane >> 4) << 3))) * APITCH
                          + ((lane >> 3) & 1) * 16);

    float acc[4][8][4];        // 4 m16-tiles x 8 n8-tiles x 4
    float s1[8], s2[8], s3[8]; // 4 m16-tiles x 2 halves
#pragma unroll
    for (int r = 0; r < 8; r++) { s1[r] = 0.f; s2[r] = 0.f; s3[r] = 0.f; }

    int nt_p = 0, kt_p = 0;
#pragma unroll
    for (int s = 0; s < STAGES - 1; s++) {
        issue_tile(sb, s, rb, nt_p, kt_p, tid);
        CP_COMMIT();
        if (++kt_p == KT_PER) { kt_p = 0; nt_p++; }
    }

    int i = 0;
    for (int nt = 0; nt < N_PASSES; nt++) {
#pragma unroll
        for (int mt = 0; mt < 4; mt++)
#pragma unroll
            for (int j = 0; j < 8; j++)
#pragma unroll
                for (int cc = 0; cc < 4; cc++) acc[mt][j][cc] = 0.f;

        for (int kt = 0; kt < KT_PER; kt++, i++) {
            CP_WAIT2();
            __syncthreads();
            if (nt_p < N_PASSES) {
                issue_tile(sb, (i + STAGES - 1) & (STAGES - 1), rb, nt_p, kt_p, tid);
                if (++kt_p == KT_PER) { kt_p = 0; nt_p++; }
            }
            CP_COMMIT();

            const uint32_t stg = sb + (uint32_t)(i & (STAGES - 1)) * STAGE_B;
#pragma unroll
            for (int k16 = 0; k16 < 2; k16++) {
                uint32_t aa[4][4], bb[4][4];
#pragma unroll
                for (int mt = 0; mt < 4; mt++)
                    LDSM4(aa[mt][0], aa[mt][1], aa[mt][2], aa[mt][3],
                          stg + a_off + mt * 16 * APITCH + k16 * 32);
#pragma unroll
                for (int np = 0; np < 4; np++)
                    LDSM4(bb[np][0], bb[np][1], bb[np][2], bb[np][3],
                          stg + b_off + np * 16 * APITCH + k16 * 32);
#pragma unroll
                for (int mt = 0; mt < 4; mt++)
#pragma unroll
                    for (int np = 0; np < 4; np++) {
                        MMA16816(acc[mt][2 * np],     aa[mt], bb[np][0], bb[np][1]);
                        MMA16816(acc[mt][2 * np + 1], aa[mt], bb[np][2], bb[np][3]);
                    }
            }
        }

        // ---- fused epilogue: bias + exact GELU + LN moments (registers) ----
        const int nb = nt * BN + wn * 64;
#pragma unroll
        for (int mt = 0; mt < 4; mt++)
#pragma unroll
            for (int j = 0; j < 8; j++)
#pragma unroll
                for (int cc = 0; cc < 4; cc++) {
                    int half = cc >> 1, cp = cc & 1;
                    int n = nb + j * 8 + (lane & 3) * 2 + cp;
                    float h = acc[mt][j][cc] + b1s[n];
                    float g = 0.5f * h * (1.0f + erff(h * 0.70710678118654752f));
                    int ridx = mt * 2 + half;
                    s1[ridx] += g;
                    s2[ridx] += g * g;
                    s3[ridx] += g * sgw[n];
                }
    }
    CP_WAIT0();

    // quad-reduce LN moments (lanes sharing rows)
#pragma unroll
    for (int r = 0; r < 8; r++) {
        s1[r] += __shfl_xor_sync(0xffffffffu, s1[r], 1);
        s1[r] += __shfl_xor_sync(0xffffffffu, s1[r], 2);
        s2[r] += __shfl_xor_sync(0xffffffffu, s2[r], 1);
        s2[r] += __shfl_xor_sync(0xffffffffu, s2[r], 2);
        s3[r] += __shfl_xor_sync(0xffffffffu, s3[r], 1);
        s3[r] += __shfl_xor_sync(0xffffffffu, s3[r], 2);
    }
    __syncthreads();

    // cross-warp (wn) partials to smem
    if ((lane & 3) == 0) {
#pragma unroll
        for (int mt = 0; mt < 4; mt++)
#pragma unroll
            for (int half = 0; half < 2; half++) {
                int ridx = mt * 2 + half;
                int rl = wm * 64 + mt * 16 + (lane >> 2) + half * 8;
                float* p = red + (wn * BM + rl) * 3;
                p[0] = s1[ridx]; p[1] = s2[ridx]; p[2] = s3[ridx];
            }
    }
    __syncthreads();

    if (tid < BM) {
        const float c1 = g_c1, c2 = g_c2, inv = 1.0f / (float)ID;
        float* p0 = red + tid * 3;
        float* p1 = red + (BM + tid) * 3;
        float t1 = p0[0] + p1[0];
        float t2 = p0[1] + p1[1];
        float t3 = p0[2] + p1[2];
        float mu   = t1 * inv;
        float var  = t2 * inv - mu * mu;
        float rstd = rsqrtf(var + LN_EPS);
        float x = rstd * (t3 - mu * c1) + c2;
        scores[rb * BM + tid] = 1.0f / (1.0f + expf(-x));
    }
}

// ------------------------------ finalize -----------------------------------
__global__ void finalize_kernel(const float* __restrict__ scores,
                                float* __restrict__ pred,
                                float* __restrict__ logits) {
    int b = blockIdx.x;
    int tid = threadIdx.x;   // 128
    float v = (tid < NTOK) ? scores[b * NTOK + tid] : 0.f;
    for (int o = 16; o; o >>= 1) v += __shfl_xor_sync(0xffffffffu, v, o);
    __shared__ float ws[4];
    __shared__ float predv;
    if ((tid & 31) == 0) ws[tid >> 5] = v;
    __syncthreads();
    if (tid == 0) {
        float s = ws[0] + ws[1] + ws[2] + ws[3];
        pred[b] = s;
        predv = s;
    }
    __syncthreads();
    if (tid < 16) {
        int aid = (int)rintf(predv);
        aid = min(max(aid, 0), 15);
        logits[b * 16 + tid] = (tid == aid) ? 1.0f : 0.0f;
    }
}

// ------------------------------ launch --------------------------------------
extern "C" void kernel_launch(void* const* d_in, const int* in_sizes, int n_in,
                              void* d_out, int out_size) {
    const float* v_emb = (const float*)d_in[0];
    const float* W1    = (const float*)d_in[1];
    const float* b1    = (const float*)d_in[2];
    const float* gamma = (const float*)d_in[3];
    const float* beta  = (const float*)d_in[4];
    const float* W2    = (const float*)d_in[5];
    const float* b2    = (const float*)d_in[6];

    float* out    = (float*)d_out;
    float* scores = out;                    // [51200]
    float* pred   = out + M_ROWS;           // [512]
    float* logits = out + M_ROWS + BATCH;   // [512*16]

    cudaFuncSetAttribute(gemm_kernel, cudaFuncAttributeMaxDynamicSharedMemorySize, SMEM_TOTAL);

    consts_kernel<<<1, 256>>>(gamma, beta, W2, b2);
    splitA_kernel<<<(M_ROWS * (HD / 4)) / 256, 256>>>(v_emb);
    splitB_kernel<<<(HD * (ID / 4)) / 256, 256>>>(W1);
    gemm_kernel<<<ROW_BLKS, 128, SMEM_TOTAL>>>(b1, gamma, W2, scores);
    finalize_kernel<<<BATCH, 128>>>(scores, pred, logits);
}

// round 7
// speedup vs baseline: 1.2981x; 1.0823x over previous
#include <cuda_runtime.h>
#include <cuda_bf16.h>
#include <math.h>
#include <stdint.h>

#define BATCH    512
#define NTOK     100
#define HD       768
#define ID       1536
#define M_ROWS   (BATCH * NTOK)     // 51200
#define BM       128
#define ROW_BLKS (M_ROWS / BM)      // 400
#define BN       128
#define N_PASSES (ID / BN)          // 12
#define KP       2304               // 3 * 768 virtual K
#define BK       64
#define KT_PER   (KP / BK)          // 36
#define TOT_KT   (KT_PER * N_PASSES) // 432
#define APITCH   144                // smem bytes per row (64 bf16 + 16 pad)
#define A_STAGE_B (BM * APITCH)     // 18432
#define B_STAGE_B (BN * APITCH)     // 18432
#define STAGE_B   (A_STAGE_B + B_STAGE_B)  // 36864
#define SM_B1S    (2 * STAGE_B)            // 73728
#define SM_SGW    (SM_B1S + ID * 4)        // 79872
#define SM_RED    (SM_SGW + ID * 4)        // 86016
#define SMEM_TOTAL (SM_RED + 2 * BM * 3 * 4)  // 89088
#define LN_EPS   1e-5f

__device__ float g_c1, g_c2;

// A2: [M][1536] bf16 = [Ah(768) | Al(768)]
__device__ __align__(16) __nv_bfloat16 A2[(size_t)M_ROWS * ID];
// Bt: [N=1536][2304] bf16 = per row n: [Bh(768) | Bl(768) | Bh(768)]
__device__ __align__(16) __nv_bfloat16 Bt[(size_t)ID * KP];

// ------------------------------- helpers -----------------------------------
__device__ __forceinline__ uint32_t smem_u32(const void* p) {
    uint32_t a;
    asm("{ .reg .u64 t; cvta.to.shared.u64 t, %1; cvt.u32.u64 %0, t; }" : "=r"(a) : "l"(p));
    return a;
}

__device__ __forceinline__ void cp16(uint32_t dst, const void* src) {
    asm volatile("cp.async.cg.shared.global [%0], [%1], 16;" :: "r"(dst), "l"(src));
}
#define CP_COMMIT() asm volatile("cp.async.commit_group;" ::: "memory")
#define CP_WAIT1()  asm volatile("cp.async.wait_group 1;" ::: "memory")
#define CP_WAIT0()  asm volatile("cp.async.wait_group 0;" ::: "memory")

#define LDSM4(r0, r1, r2, r3, addr) \
    asm volatile("ldmatrix.sync.aligned.m8n8.x4.shared.b16 {%0,%1,%2,%3}, [%4];" \
                 : "=r"(r0), "=r"(r1), "=r"(r2), "=r"(r3) : "r"(addr))

#define MMA16816(d, a, bx, by) \
    asm volatile("mma.sync.aligned.m16n8k16.row.col.f32.bf16.bf16.f32 " \
                 "{%0,%1,%2,%3},{%4,%5,%6,%7},{%8,%9},{%0,%1,%2,%3};" \
                 : "+f"((d)[0]), "+f"((d)[1]), "+f"((d)[2]), "+f"((d)[3]) \
                 : "r"((a)[0]), "r"((a)[1]), "r"((a)[2]), "r"((a)[3]), "r"(bx), "r"(by))

// ------------------------------ prep kernels -------------------------------
__global__ void consts_kernel(const float* __restrict__ gamma,
                              const float* __restrict__ beta,
                              const float* __restrict__ W2,
                              const float* __restrict__ b2) {
    __shared__ float s1s[8], s2s[8];
    int tid = threadIdx.x;
    float c1 = 0.f, c2 = 0.f;
    for (int i = tid; i < ID; i += blockDim.x) {
        float w = W2[i];
        c1 += gamma[i] * w;
        c2 += beta[i] * w;
    }
    for (int o = 16; o; o >>= 1) {
        c1 += __shfl_xor_sync(0xffffffffu, c1, o);
        c2 += __shfl_xor_sync(0xffffffffu, c2, o);
    }
    if ((tid & 31) == 0) { s1s[tid >> 5] = c1; s2s[tid >> 5] = c2; }
    __syncthreads();
    if (tid == 0) {
        float a = 0.f, b = 0.f;
        for (int w = 0; w < (int)(blockDim.x >> 5); w++) { a += s1s[w]; b += s2s[w]; }
        g_c1 = a;
        g_c2 = b + b2[0];
    }
}

__global__ void splitA_kernel(const float* __restrict__ A) {
    size_t idx = (size_t)blockIdx.x * 256 + threadIdx.x;
    int m  = (int)(idx / (HD / 4));
    int k4 = (int)(idx % (HD / 4)) * 4;
    float4 v = *(const float4*)(A + (size_t)m * HD + k4);
    float vs[4] = {v.x, v.y, v.z, v.w};
    __nv_bfloat16 h[4], l[4];
#pragma unroll
    for (int e = 0; e < 4; e++) {
        h[e] = __float2bfloat16(vs[e]);
        l[e] = __float2bfloat16(vs[e] - __bfloat162float(h[e]));
    }
    __nv_bfloat162* dh = (__nv_bfloat162*)(A2 + (size_t)m * ID + k4);
    __nv_bfloat162* dl = (__nv_bfloat162*)(A2 + (size_t)m * ID + HD + k4);
    dh[0] = __halves2bfloat162(h[0], h[1]);
    dh[1] = __halves2bfloat162(h[2], h[3]);
    dl[0] = __halves2bfloat162(l[0], l[1]);
    dl[1] = __halves2bfloat162(l[2], l[3]);
}

__global__ void splitB_kernel(const float* __restrict__ W1) {
    int idx = blockIdx.x * 256 + threadIdx.x;
    int k  = idx / (ID / 4);
    int n4 = (idx % (ID / 4)) * 4;
    float4 v = *(const float4*)(W1 + (size_t)k * ID + n4);
    float vs[4] = {v.x, v.y, v.z, v.w};
#pragma unroll
    for (int e = 0; e < 4; e++) {
        int n = n4 + e;
        __nv_bfloat16 h = __float2bfloat16(vs[e]);
        __nv_bfloat16 l = __float2bfloat16(vs[e] - __bfloat162float(h));
        size_t base = (size_t)n * KP + k;
        Bt[base]        = h;
        Bt[base + 768]  = l;
        Bt[base + 1536] = h;
    }
}

// ------------------------------ GEMM stage issue ----------------------------
// BK=64: per N-pass kt 0..35. kt 0-11: Ah cols, 12-23: Ah cols, 24-35: Al cols.
__device__ __forceinline__ void issue_tile(uint32_t sb, int s, int rb, int nt, int kt, int tid) {
    int acol = (kt % 12) * 64 + (kt >= 24 ? HD : 0);
    const __nv_bfloat16* gA = A2 + (size_t)rb * BM * ID + acol;
    uint32_t dA = sb + s * STAGE_B;
#pragma unroll
    for (int j = 0; j < 8; j++) {
        int c = tid + 128 * j;          // 0..1023
        int row = c >> 3, c16 = c & 7;
        cp16(dA + row * APITCH + c16 * 16, gA + (size_t)row * ID + c16 * 8);
    }
    const __nv_bfloat16* gB = Bt + (size_t)nt * BN * KP + kt * 64;
    uint32_t dB = sb + s * STAGE_B + A_STAGE_B;
#pragma unroll
    for (int j = 0; j < 8; j++) {
        int c = tid + 128 * j;          // 0..1023
        int row = c >> 3, c16 = c & 7;
        cp16(dB + row * APITCH + c16 * 16, gB + (size_t)row * KP + c16 * 8);
    }
}

// ------------------------------ GEMM kernel --------------------------------
// 128 threads (4 warps): warp grid 2(M) x 2(N), warp tile 64x64, mma m16n8k16.
// BK=64 (4 k16 per kt), 2-stage cp.async, register double-buffered ldmatrix.
__global__ __launch_bounds__(128, 2)
void gemm_kernel(const float* __restrict__ b1,
                 const float* __restrict__ gamma,
                 const float* __restrict__ W2,
                 float* __restrict__ scores) {
    extern __shared__ char smem[];
    const uint32_t sb = smem_u32(smem);
    float* b1s = (float*)(smem + SM_B1S);
    float* sgw = (float*)(smem + SM_SGW);
    float* red = (float*)(smem + SM_RED);   // [2][128][3]
    const int tid = threadIdx.x, wid = tid >> 5, lane = tid & 31;
    const int wm = wid & 1, wn = wid >> 1;
    const int rb = blockIdx.x;

    for (int i = tid; i < ID; i += 128) {
        b1s[i] = b1[i];
        sgw[i] = gamma[i] * W2[i];
    }

    const uint32_t a_off = (uint32_t)((wm * 64 + (lane & 15)) * APITCH + (lane >> 4) * 16);
    const uint32_t b_off = (uint32_t)(A_STAGE_B
                          + (wn * 64 + ((lane & 7) | ((lane >> 4) << 3))) * APITCH
                          + ((lane >> 3) & 1) * 16);

    float acc[4][8][4];        // 4 m16-tiles x 8 n8-tiles x 4
    float s1[8], s2[8], s3[8];
#pragma unroll
    for (int r = 0; r < 8; r++) { s1[r] = 0.f; s2[r] = 0.f; s3[r] = 0.f; }

    // prologue: fill both stages
    int nt_p = 0, kt_p = 0;
#pragma unroll
    for (int s = 0; s < 2; s++) {
        issue_tile(sb, s, rb, nt_p, kt_p, tid);
        CP_COMMIT();
        if (++kt_p == KT_PER) { kt_p = 0; nt_p++; }
    }

    int i = 0;
    for (int nt = 0; nt < N_PASSES; nt++) {
#pragma unroll
        for (int mt = 0; mt < 4; mt++)
#pragma unroll
            for (int j = 0; j < 8; j++)
#pragma unroll
                for (int cc = 0; cc < 4; cc++) acc[mt][j][cc] = 0.f;

        for (int kt = 0; kt < KT_PER; kt++, i++) {
            CP_WAIT1();
            __syncthreads();
            const uint32_t stg = sb + (uint32_t)(i & 1) * STAGE_B;

            uint32_t aa[2][4][4], bb[2][4][4];
            // prime k16 = 0 fragments
#pragma unroll
            for (int mt = 0; mt < 4; mt++)
                LDSM4(aa[0][mt][0], aa[0][mt][1], aa[0][mt][2], aa[0][mt][3],
                      stg + a_off + mt * 16 * APITCH);
#pragma unroll
            for (int np = 0; np < 4; np++)
                LDSM4(bb[0][np][0], bb[0][np][1], bb[0][np][2], bb[0][np][3],
                      stg + b_off + np * 16 * APITCH);

#pragma unroll
            for (int k16 = 0; k16 < 4; k16++) {
                const int cur = k16 & 1, nxt = cur ^ 1;
                if (k16 < 3) {
#pragma unroll
                    for (int mt = 0; mt < 4; mt++)
                        LDSM4(aa[nxt][mt][0], aa[nxt][mt][1], aa[nxt][mt][2], aa[nxt][mt][3],
                              stg + a_off + mt * 16 * APITCH + (k16 + 1) * 32);
#pragma unroll
                    for (int np = 0; np < 4; np++)
                        LDSM4(bb[nxt][np][0], bb[nxt][np][1], bb[nxt][np][2], bb[nxt][np][3],
                              stg + b_off + np * 16 * APITCH + (k16 + 1) * 32);
                }
#pragma unroll
                for (int mt = 0; mt < 4; mt++)
#pragma unroll
                    for (int np = 0; np < 4; np++) {
                        MMA16816(acc[mt][2 * np],     aa[cur][mt], bb[cur][np][0], bb[cur][np][1]);
                        MMA16816(acc[mt][2 * np + 1], aa[cur][mt], bb[cur][np][2], bb[cur][np][3]);
                    }
            }

            __syncthreads();   // all warps done reading this stage before refill
            if (nt_p < N_PASSES) {
                issue_tile(sb, i & 1, rb, nt_p, kt_p, tid);
                if (++kt_p == KT_PER) { kt_p = 0; nt_p++; }
            }
            CP_COMMIT();
        }

        // ---- fused epilogue: bias + exact GELU + LN moments (registers) ----
        const int nb = nt * BN + wn * 64;
#pragma unroll
        for (int mt = 0; mt < 4; mt++)
#pragma unroll
            for (int j = 0; j < 8; j++)
#pragma unroll
                for (int cc = 0; cc < 4; cc++) {
                    int half = cc >> 1, cp = cc & 1;
                    int n = nb + j * 8 + (lane & 3) * 2 + cp;
                    float h = acc[mt][j][cc] + b1s[n];
                    float g = 0.5f * h * (1.0f + erff(h * 0.70710678118654752f));
                    int ridx = mt * 2 + half;
                    s1[ridx] += g;
                    s2[ridx] += g * g;
                    s3[ridx] += g * sgw[n];
                }
    }
    CP_WAIT0();

    // quad-reduce LN moments (lanes sharing rows)
#pragma unroll
    for (int r = 0; r < 8; r++) {
        s1[r] += __shfl_xor_sync(0xffffffffu, s1[r], 1);
        s1[r] += __shfl_xor_sync(0xffffffffu, s1[r], 2);
        s2[r] += __shfl_xor_sync(0xffffffffu, s2[r], 1);
        s2[r] += __shfl_xor_sync(0xffffffffu, s2[r], 2);
        s3[r] += __shfl_xor_sync(0xffffffffu, s3[r], 1);
        s3[r] += __shfl_xor_sync(0xffffffffu, s3[r], 2);
    }
    __syncthreads();

    if ((lane & 3) == 0) {
#pragma unroll
        for (int mt = 0; mt < 4; mt++)
#pragma unroll
            for (int half = 0; half < 2; half++) {
                int ridx = mt * 2 + half;
                int rl = wm * 64 + mt * 16 + (lane >> 2) + half * 8;
                float* p = red + (wn * BM + rl) * 3;
                p[0] = s1[ridx]; p[1] = s2[ridx]; p[2] = s3[ridx];
            }
    }
    __syncthreads();

    if (tid < BM) {
        const float c1 = g_c1, c2 = g_c2, inv = 1.0f / (float)ID;
        float* p0 = red + tid * 3;
        float* p1 = red + (BM + tid) * 3;
        float t1 = p0[0] + p1[0];
        float t2 = p0[1] + p1[1];
        float t3 = p0[2] + p1[2];
        float mu   = t1 * inv;
        float var  = t2 * inv - mu * mu;
        float rstd = rsqrtf(var + LN_EPS);
        float x = rstd * (t3 - mu * c1) + c2;
        scores[rb * BM + tid] = 1.0f / (1.0f + expf(-x));
    }
}

// ------------------------------ finalize -----------------------------------
__global__ void finalize_kernel(const float* __restrict__ scores,
                                float* __restrict__ pred,
                                float* __restrict__ logits) {
    int b = blockIdx.x;
    int tid = threadIdx.x;   // 128
    float v = (tid < NTOK) ? scores[b * NTOK + tid] : 0.f;
    for (int o = 16; o; o >>= 1) v += __shfl_xor_sync(0xffffffffu, v, o);
    __shared__ float ws[4];
    __shared__ float predv;
    if ((tid & 31) == 0) ws[tid >> 5] = v;
    __syncthreads();
    if (tid == 0) {
        float s = ws[0] + ws[1] + ws[2] + ws[3];
        pred[b] = s;
        predv = s;
    }
    __syncthreads();
    if (tid < 16) {
        int aid = (int)rintf(predv);
        aid = min(max(aid, 0), 15);
        logits[b * 16 + tid] = (tid == aid) ? 1.0f : 0.0f;
    }
}

// ------------------------------ launch --------------------------------------
extern "C" void kernel_launch(void* const* d_in, const int* in_sizes, int n_in,
                              void* d_out, int out_size) {
    const float* v_emb = (const float*)d_in[0];
    const float* W1    = (const float*)d_in[1];
    const float* b1    = (const float*)d_in[2];
    const float* gamma = (const float*)d_in[3];
    const float* beta  = (const float*)d_in[4];
    const float* W2    = (const float*)d_in[5];
    const float* b2    = (const float*)d_in[6];

    float* out    = (float*)d_out;
    float* scores = out;                    // [51200]
    float* pred   = out + M_ROWS;           // [512]
    float* logits = out + M_ROWS + BATCH;   // [512*16]

    cudaFuncSetAttribute(gemm_kernel, cudaFuncAttributeMaxDynamicSharedMemorySize, SMEM_TOTAL);

    consts_kernel<<<1, 256>>>(gamma, beta, W2, b2);
    splitA_kernel<<<(M_ROWS * (HD / 4)) / 256, 256>>>(v_emb);
    splitB_kernel<<<(HD * (ID / 4)) / 256, 256>>>(W1);
    gemm_kernel<<<ROW_BLKS, 128, SMEM_TOTAL>>>(b1, gamma, W2, scores);
    finalize_kernel<<<BATCH, 128>>>(scores, pred, logits);
}